// round 16
// baseline (speedup 1.0000x reference)
#include <cuda_runtime.h>
#include <cuda_bf16.h>
#include <cstdint>

#define B_SZ 4096
#define D_SZ 1024
#define EPS_F 1e-7f

#define BM 128
#define NKB 16                          // 16 k-blocks of 64 (layout unit)
#define A_TILE_B (BM * 128)             // 16384 B (bf16, 128 rows x 128B)
#define B_TILE_B (256 * 128)            // 32768 B (bf16, 256 rows x 128B)
#define A_CHUNK_B (2 * A_TILE_B)        // 32768 B (BK=128)
#define B_CHUNK_B (2 * B_TILE_B)        // 65536 B
#define STAGE_B  (A_CHUNK_B + B_CHUNK_B) // 98304 B
#define NSTAGE 2
#define SM_CTRL (NSTAGE * STAGE_B)      // 196608
#define DSMEM_TOTAL (SM_CTRL + 128)
#define NSM 152
#define NFULL 456                       // 3 * 152 full 128x256 tiles
#define NHALF 112                       // (512-456)*2 half 128x128 tiles
#define NTHREADS 288                    // 8 compute warps (2x4, 64x64) + 1 producer
#define NCW 8

template <int N> struct Int { static constexpr int value = N; };

// ---- scratch (allocation-free rule: __device__ globals) -------------------
__device__ __align__(1024) __nv_bfloat16 g_ln[B_SZ * D_SZ];
__device__ __align__(1024) __nv_bfloat16 g_rn[B_SZ * D_SZ];
__device__ float g_rowsum[B_SZ];
__device__ float g_colsum[B_SZ];
__device__ float g_diag[B_SZ];
__device__ int   g_done;

// ---------------------------------------------------------------------------
__device__ __forceinline__ uint32_t smem_u32(const void* p) {
    uint32_t a;
    asm("{ .reg .u64 t; cvta.to.shared.u64 t, %1; cvt.u32.u64 %0, t; }"
        : "=r"(a) : "l"(p));
    return a;
}

__device__ __forceinline__ float fast_exp(float x) {
    float y = x * 1.4426950408889634f;
    float t = y + 12582912.0f;
    int   n = __float_as_int(t) - 0x4B400000;
    float f = y - (t - 12582912.0f);
    float p = 1.3333558e-3f;
    p = fmaf(p, f, 9.6181291e-3f);
    p = fmaf(p, f, 5.5504109e-2f);
    p = fmaf(p, f, 2.4022651e-1f);
    p = fmaf(p, f, 6.9314718e-1f);
    p = fmaf(p, f, 1.0f);
    return p * __int_as_float((n + 127) << 23);
}

// ---- mbarrier / bulk-copy helpers (plain sm_90 PTX) -----------------------
__device__ __forceinline__ void mb_init(uint32_t a, uint32_t cnt) {
    asm volatile("mbarrier.init.shared.b64 [%0], %1;" :: "r"(a), "r"(cnt) : "memory");
}
__device__ __forceinline__ void mb_expect(uint32_t a, uint32_t bytes) {
    asm volatile("mbarrier.arrive.expect_tx.shared.b64 _, [%0], %1;"
                 :: "r"(a), "r"(bytes) : "memory");
}
__device__ __forceinline__ void mb_arrive(uint32_t a) {
    asm volatile("mbarrier.arrive.shared.b64 _, [%0];" :: "r"(a) : "memory");
}
__device__ __forceinline__ void mb_wait(uint32_t a, uint32_t parity) {
    asm volatile(
        "{\n\t.reg .pred P;\n\t"
        "WL_%=:\n\t"
        "mbarrier.try_wait.parity.acquire.cta.shared::cta.b64 P, [%0], %1, 0x989680;\n\t"
        "@P bra.uni WD_%=;\n\t"
        "bra.uni WL_%=;\n\t"
        "WD_%=:\n\t}"
        :: "r"(a), "r"(parity) : "memory");
}
__device__ __forceinline__ void bulk_g2s(uint32_t dst, const void* src,
                                         uint32_t bytes, uint32_t mbar) {
    asm volatile(
        "cp.async.bulk.shared::cluster.global.mbarrier::complete_tx::bytes "
        "[%0], [%1], %2, [%3];"
        :: "r"(dst), "l"(src), "r"(bytes), "r"(mbar) : "memory");
}

// ---- mma / ldmatrix -------------------------------------------------------
__device__ __forceinline__ void mma16816(float d[4], const uint32_t a[4],
                                         const uint32_t b[2]) {
    asm volatile(
        "mma.sync.aligned.m16n8k16.row.col.f32.bf16.bf16.f32 "
        "{%0,%1,%2,%3}, {%4,%5,%6,%7}, {%8,%9}, {%0,%1,%2,%3};\n"
        : "+f"(d[0]), "+f"(d[1]), "+f"(d[2]), "+f"(d[3])
        : "r"(a[0]), "r"(a[1]), "r"(a[2]), "r"(a[3]), "r"(b[0]), "r"(b[1]));
}
__device__ __forceinline__ void ldsm_x4(uint32_t& r0, uint32_t& r1,
                                        uint32_t& r2, uint32_t& r3,
                                        uint32_t addr) {
    asm volatile("ldmatrix.sync.aligned.m8n8.x4.shared.b16 {%0,%1,%2,%3}, [%4];"
                 : "=r"(r0), "=r"(r1), "=r"(r2), "=r"(r3) : "r"(addr));
}

// ---------------------------------------------------------------------------
// Kernel 1: l2-normalize rows -> bf16 in SW128-swizzled tile layout.
// ---------------------------------------------------------------------------
__global__ void normalize_kernel(const float* __restrict__ left,
                                 const float* __restrict__ right) {
    int warp = threadIdx.x >> 5, lane = threadIdx.x & 31;
    int row = blockIdx.x * 8 + warp;          // 0..8191
    bool isL = row < B_SZ;
    int r = isL ? row : row - B_SZ;
    const float* src = (isL ? left : right) + (size_t)r * D_SZ;

    float4 v[8];
    float ss = 0.0f;
    #pragma unroll
    for (int i = 0; i < 8; ++i) {
        v[i] = ((const float4*)src)[lane + 32 * i];
        ss += v[i].x * v[i].x + v[i].y * v[i].y + v[i].z * v[i].z + v[i].w * v[i].w;
    }
    #pragma unroll
    for (int o = 16; o > 0; o >>= 1) ss += __shfl_xor_sync(0xffffffffu, ss, o);
    float inv = rsqrtf(fmaxf(ss, EPS_F));

    char* base;
    int rr;
    size_t tile_b;
    if (isL) {
        base = (char*)g_ln + (size_t)(r >> 7) * NKB * A_TILE_B;
        rr = r & 127;
        tile_b = A_TILE_B;
    } else {
        base = (char*)g_rn + (size_t)(r >> 8) * NKB * B_TILE_B;
        rr = r & 255;
        tile_b = B_TILE_B;
    }

    #pragma unroll
    for (int i = 0; i < 8; ++i) {
        __nv_bfloat162 h0 = __floats2bfloat162_rn(v[i].x * inv, v[i].y * inv);
        __nv_bfloat162 h1 = __floats2bfloat162_rn(v[i].z * inv, v[i].w * inv);
        uint2 pack;
        pack.x = *(const unsigned int*)&h0;
        pack.y = *(const unsigned int*)&h1;
        int f = lane + 32 * i;                // float4 index in row, 0..255
        int kb = f >> 4;                      // k-block 0..15
        int kc = (f & 15) * 8;                // byte offset in [0,128)
        uint32_t off = (uint32_t)(rr * 128 + (kc ^ ((rr & 7) << 4)));
        *(uint2*)(base + (size_t)kb * tile_b + off) = pack;
    }
    if (lane == 0 && isL) { g_rowsum[r] = 0.0f; g_colsum[r] = 0.0f; }
    if (blockIdx.x == 0 && threadIdx.x == 0) g_done = 0;
}

// ---------------------------------------------------------------------------
// Kernel 2: persistent bf16 GEMM. 456 full 128x256 tiles (3 per CTA) + 112
// half 128x128 tiles (CTAs 0..111). 8 compute warps (2x4, 64x64 warp tiles,
// B-fragment double buffering) + 1 producer warp, 2-stage BK=128 pipeline.
// Fused exp / rowsum / colsum / diag epilogue; last CTA computes the loss.
// ---------------------------------------------------------------------------
__global__ void __launch_bounds__(NTHREADS, 1)
gemm_stats_kernel(const float* __restrict__ temperature,
                  float* __restrict__ out) {
    extern __shared__ char dsm[];
    __shared__ float s_rl[NCW + 1], s_rr[NCW + 1];
    __shared__ int s_last;
    uint32_t sbase = smem_u32(dsm);
    const int tid = threadIdx.x, warp = tid >> 5, lane = tid & 31;
    const int c = blockIdx.x;

    uint32_t mb_full  = sbase + SM_CTRL;        // 2 x 8B
    uint32_t mb_empty = sbase + SM_CTRL + 32;   // 2 x 8B

    if (tid == 0) {
        #pragma unroll
        for (int s = 0; s < NSTAGE; ++s) {
            mb_init(mb_full + 8 * s, 1);
            mb_init(mb_empty + 8 * s, NCW);
        }
    }
    __syncthreads();

    if (warp == NCW) {
        // ---------------- producer warp ----------------
        if (lane == 0) {
            int g = 0;
            for (int j = 0; j < 3; ++j) {                  // full tiles
                int t = c + NSM * j;
                int bi = t >> 4, bj = t & 15;
                for (int kc = 0; kc < 8; ++kc, ++g) {
                    int s = g & 1;
                    if (g >= NSTAGE)
                        mb_wait(mb_empty + 8 * s, ((g >> 1) - 1) & 1);
                    uint32_t dst = sbase + s * STAGE_B;
                    mb_expect(mb_full + 8 * s, STAGE_B);
                    bulk_g2s(dst,
                             (const char*)g_ln + (size_t)(bi * 16 + kc * 2) * A_TILE_B,
                             A_CHUNK_B, mb_full + 8 * s);
                    bulk_g2s(dst + A_CHUNK_B,
                             (const char*)g_rn + (size_t)(bj * 16 + kc * 2) * B_TILE_B,
                             B_CHUNK_B, mb_full + 8 * s);
                }
            }
            if (c < NHALF) {                               // one half tile
                int t2 = NFULL + (c >> 1);
                int bi = t2 >> 4, bj = t2 & 15, h = c & 1;
                for (int kc = 0; kc < 8; ++kc, ++g) {
                    int s = g & 1;
                    mb_wait(mb_empty + 8 * s, ((g >> 1) - 1) & 1);
                    uint32_t dst = sbase + s * STAGE_B;
                    mb_expect(mb_full + 8 * s, A_CHUNK_B + 32768u);
                    bulk_g2s(dst,
                             (const char*)g_ln + (size_t)(bi * 16 + kc * 2) * A_TILE_B,
                             A_CHUNK_B, mb_full + 8 * s);
                    bulk_g2s(dst + A_CHUNK_B,
                             (const char*)g_rn + (size_t)(bj * 16 + kc * 2) * B_TILE_B
                                               + (size_t)h * 16384,
                             16384u, mb_full + 8 * s);
                    bulk_g2s(dst + A_CHUNK_B + 16384u,
                             (const char*)g_rn + (size_t)(bj * 16 + kc * 2 + 1) * B_TILE_B
                                               + (size_t)h * 16384,
                             16384u, mb_full + 8 * s);
                }
            }
        }
    } else {
        // ---------------- compute warps (2x4 grid, 64x64 full) ----------
        const int wr = warp >> 2;    // 0..1  (64-row slab)
        const int wc = warp & 3;     // 0..3
        const int grp = lane >> 2;   // 0..7
        const int qid = lane & 3;    // 0..3
        const float scale = __expf(temperature[0]);

        const int a_row_in = (lane & 7) + ((lane >> 3) & 1) * 8;
        const uint32_t a_koff = ((lane >> 4) & 1) * 16;
        const int b_n_in = (lane & 7) + ((lane >> 4) & 1) * 8;
        const uint32_t b_koff = ((lane >> 3) & 1) * 16;
        const uint32_t a_sw = (uint32_t)((a_row_in & 7) << 4);
        const uint32_t b_sw = (uint32_t)((b_n_in & 7) << 4);
        const uint32_t a_rowbase = (uint32_t)((wr * 64 + a_row_in) * 128);

        int g = 0;

        auto run_tile = [&](int bi, int col_base, auto ntc) {
            constexpr int NTN = decltype(ntc)::value;     // 8 (full) / 4 (half)
            constexpr int WCW = 8 * NTN;                  // warp col width 64/32
            constexpr int PRN = NTN / 2;                  // B ldsm count 4/2
            constexpr int WIDTH = 32 * NTN;               // tile col width 256/128
            constexpr uint32_t SUBB = (uint32_t)(WIDTH * 128); // B k64 sub-tile bytes
            const uint32_t b_rowbase = (uint32_t)((wc * WCW + b_n_in) * 128);

            float acc[4][NTN][4];
            #pragma unroll
            for (int mt = 0; mt < 4; ++mt)
                #pragma unroll
                for (int nt = 0; nt < NTN; ++nt)
                    #pragma unroll
                    for (int k = 0; k < 4; ++k) acc[mt][nt][k] = 0.0f;

            for (int kc = 0; kc < 8; ++kc, ++g) {
                int s = g & 1;
                mb_wait(mb_full + 8 * s, (g >> 1) & 1);

                uint32_t sA = sbase + s * STAGE_B;
                uint32_t sB = sA + A_CHUNK_B;

                uint32_t bf[2][NTN][2];

                auto loadB = [&](uint32_t dst[NTN][2], int kk) {
                    uint32_t subB = (uint32_t)(kk >> 2) * SUBB;
                    uint32_t b_col = ((b_koff | (uint32_t)((kk & 3) << 5)) ^ b_sw) + subB;
                    #pragma unroll
                    for (int pr = 0; pr < PRN; ++pr) {
                        uint32_t r0, r1, r2, r3;
                        ldsm_x4(r0, r1, r2, r3,
                                sB + b_rowbase + pr * 2048 + b_col);
                        dst[2 * pr][0] = r0;      dst[2 * pr][1] = r1;
                        dst[2 * pr + 1][0] = r2;  dst[2 * pr + 1][1] = r3;
                    }
                };

                loadB(bf[0], 0);
                #pragma unroll
                for (int kk = 0; kk < 8; ++kk) {
                    int cur = kk & 1;
                    if (kk < 7) loadB(bf[cur ^ 1], kk + 1);   // prefetch next
                    uint32_t subA = (uint32_t)(kk >> 2) * (uint32_t)A_TILE_B;
                    uint32_t a_col = ((a_koff | (uint32_t)((kk & 3) << 5)) ^ a_sw) + subA;
                    #pragma unroll
                    for (int mt = 0; mt < 4; ++mt) {
                        uint32_t af[4];
                        ldsm_x4(af[0], af[1], af[2], af[3],
                                sA + a_rowbase + mt * 2048 + a_col);
                        #pragma unroll
                        for (int nt = 0; nt < NTN; ++nt)
                            mma16816(acc[mt][nt], af, bf[cur][nt]);
                    }
                }
                if (lane == 0) mb_arrive(mb_empty + 8 * s);
            }

            // ---- per-tile epilogue ----
            #pragma unroll
            for (int mt = 0; mt < 4; ++mt)
                #pragma unroll
                for (int nt = 0; nt < NTN; ++nt)
                    #pragma unroll
                    for (int k = 0; k < 4; ++k)
                        acc[mt][nt][k] = fast_exp(fmaf(acc[mt][nt][k], scale, -scale));

            // row sums
            #pragma unroll
            for (int mt = 0; mt < 4; ++mt) {
                float s0 = 0.0f, s1 = 0.0f;
                #pragma unroll
                for (int nt = 0; nt < NTN; ++nt) {
                    s0 += acc[mt][nt][0] + acc[mt][nt][1];
                    s1 += acc[mt][nt][2] + acc[mt][nt][3];
                }
                s0 += __shfl_xor_sync(0xffffffffu, s0, 1);
                s0 += __shfl_xor_sync(0xffffffffu, s0, 2);
                s1 += __shfl_xor_sync(0xffffffffu, s1, 1);
                s1 += __shfl_xor_sync(0xffffffffu, s1, 2);
                if (qid == 0) {
                    int row = bi * BM + wr * 64 + mt * 16 + grp;
                    atomicAdd(&g_rowsum[row], s0);
                    atomicAdd(&g_rowsum[row + 8], s1);
                }
            }

            // col sums
            #pragma unroll
            for (int nt = 0; nt < NTN; ++nt) {
                float t0 = 0.0f, t1 = 0.0f;
                #pragma unroll
                for (int mt = 0; mt < 4; ++mt) {
                    t0 += acc[mt][nt][0] + acc[mt][nt][2];
                    t1 += acc[mt][nt][1] + acc[mt][nt][3];
                }
                t0 += __shfl_xor_sync(0xffffffffu, t0, 4);
                t0 += __shfl_xor_sync(0xffffffffu, t0, 8);
                t0 += __shfl_xor_sync(0xffffffffu, t0, 16);
                t1 += __shfl_xor_sync(0xffffffffu, t1, 4);
                t1 += __shfl_xor_sync(0xffffffffu, t1, 8);
                t1 += __shfl_xor_sync(0xffffffffu, t1, 16);
                if (grp == 0) {
                    int col = col_base + wc * WCW + nt * 8 + 2 * qid;
                    atomicAdd(&g_colsum[col], t0);
                    atomicAdd(&g_colsum[col + 1], t1);
                }
            }

            // diagonal: global row bi*128+lrow == global col col_base+lcol
            int doff = bi * BM - col_base;
            if (doff > -BM && doff < WIDTH) {
                #pragma unroll
                for (int mt = 0; mt < 4; ++mt) {
                    int lrow = wr * 64 + mt * 16 + grp;
                    #pragma unroll
                    for (int nt = 0; nt < NTN; ++nt) {
                        int lcol = wc * WCW + nt * 8 + 2 * qid;
                        if (lcol == lrow + doff)         g_diag[bi * BM + lrow]     = acc[mt][nt][0];
                        if (lcol + 1 == lrow + doff)     g_diag[bi * BM + lrow]     = acc[mt][nt][1];
                        if (lcol == lrow + 8 + doff)     g_diag[bi * BM + lrow + 8] = acc[mt][nt][2];
                        if (lcol + 1 == lrow + 8 + doff) g_diag[bi * BM + lrow + 8] = acc[mt][nt][3];
                    }
                }
            }
        };

        for (int j = 0; j < 3; ++j) {
            int t = c + NSM * j;
            run_tile(t >> 4, (t & 15) * 256, Int<8>{});
        }
        if (c < NHALF) {
            int t2 = NFULL + (c >> 1);
            run_tile(t2 >> 4, (t2 & 15) * 256 + (c & 1) * 128, Int<4>{});
        }
    }

    // ---- fused finalize: last CTA computes traces + loss ----
    __threadfence();
    __syncthreads();
    if (tid == 0) s_last = (atomicAdd(&g_done, 1) == NSM - 1) ? 1 : 0;
    __syncthreads();
    if (s_last) {
        float tl = 0.0f, tr = 0.0f;
        for (int i = tid; i < B_SZ; i += NTHREADS) {
            float d = __ldcg(&g_diag[i]);
            tl += __fdividef(d, __ldcg(&g_rowsum[i]));
            tr += __fdividef(d, __ldcg(&g_colsum[i]));
        }
        #pragma unroll
        for (int o = 16; o > 0; o >>= 1) {
            tl += __shfl_xor_sync(0xffffffffu, tl, o);
            tr += __shfl_xor_sync(0xffffffffu, tr, o);
        }
        if (lane == 0) { s_rl[warp] = tl; s_rr[warp] = tr; }
        __syncthreads();
        if (tid == 0) {
            float TL = 0.0f, TR = 0.0f;
            #pragma unroll
            for (int w = 0; w < NCW + 1; ++w) { TL += s_rl[w]; TR += s_rr[w]; }
            float logeps = logf(EPS_F);
            float log1m  = logf(1.0f - EPS_F);
            float ll = -(TL * log1m + ((float)B_SZ - TL) * logeps);
            float lr = -(TR * log1m + ((float)B_SZ - TR) * logeps);
            out[0] = (ll + lr) * 0.5f / (float)B_SZ;
        }
    }
}

// ---------------------------------------------------------------------------
extern "C" void kernel_launch(void* const* d_in, const int* in_sizes, int n_in,
                              void* d_out, int out_size) {
    const float* left  = (const float*)d_in[0];
    const float* right = (const float*)d_in[1];
    const float* temp  = (const float*)d_in[2];

    static bool attr_set = false;
    if (!attr_set) {
        cudaFuncSetAttribute(gemm_stats_kernel,
                             cudaFuncAttributeMaxDynamicSharedMemorySize,
                             DSMEM_TOTAL);
        attr_set = true;
    }

    normalize_kernel<<<1024, 256>>>(left, right);
    gemm_stats_kernel<<<NSM, NTHREADS, DSMEM_TOTAL>>>(temp, (float*)d_out);
}

// round 17
// speedup vs baseline: 1.0460x; 1.0460x over previous
#include <cuda_runtime.h>
#include <cuda_bf16.h>
#include <cstdint>

#define B_SZ 4096
#define D_SZ 1024
#define EPS_F 1e-7f

#define BM 128
#define NKB 16                          // 16 k-blocks of 64 (layout unit)
#define A_TILE_B (BM * 128)             // 16384 B (bf16, 128 rows x 128B)
#define B_TILE_B (256 * 128)            // 32768 B (bf16, 256 rows x 128B)
#define A_CHUNK_B (2 * A_TILE_B)        // 32768 B (BK=128)
#define B_CHUNK_B (2 * B_TILE_B)        // 65536 B
#define STAGE_B  (A_CHUNK_B + B_CHUNK_B) // 98304 B
#define NSTAGE 2
#define SM_CTRL (NSTAGE * STAGE_B)      // 196608
#define DSMEM_TOTAL (SM_CTRL + 128)
#define NSM 152
#define NFULL 456                       // 3 * 152 full 128x256 tiles
#define NHALF 112                       // (512-456)*2 half 128x128 tiles
#define NTHREADS 544                    // 16 compute warps + 1 producer warp
#define NCW 16

template <int N> struct Int { static constexpr int value = N; };

// ---- scratch (allocation-free rule: __device__ globals) -------------------
__device__ __align__(1024) __nv_bfloat16 g_ln[B_SZ * D_SZ];
__device__ __align__(1024) __nv_bfloat16 g_rn[B_SZ * D_SZ];
__device__ float g_rowsum[B_SZ];
__device__ float g_colsum[B_SZ];
__device__ float g_diag[B_SZ];
__device__ int   g_done;

// ---------------------------------------------------------------------------
__device__ __forceinline__ uint32_t smem_u32(const void* p) {
    uint32_t a;
    asm("{ .reg .u64 t; cvta.to.shared.u64 t, %1; cvt.u32.u64 %0, t; }"
        : "=r"(a) : "l"(p));
    return a;
}

__device__ __forceinline__ float fast_exp(float x) {
    float y = x * 1.4426950408889634f;
    float t = y + 12582912.0f;
    int   n = __float_as_int(t) - 0x4B400000;
    float f = y - (t - 12582912.0f);
    float p = 1.3333558e-3f;
    p = fmaf(p, f, 9.6181291e-3f);
    p = fmaf(p, f, 5.5504109e-2f);
    p = fmaf(p, f, 2.4022651e-1f);
    p = fmaf(p, f, 6.9314718e-1f);
    p = fmaf(p, f, 1.0f);
    return p * __int_as_float((n + 127) << 23);
}

// ---- mbarrier / bulk-copy helpers (plain sm_90 PTX) -----------------------
__device__ __forceinline__ void mb_init(uint32_t a, uint32_t cnt) {
    asm volatile("mbarrier.init.shared.b64 [%0], %1;" :: "r"(a), "r"(cnt) : "memory");
}
__device__ __forceinline__ void mb_expect(uint32_t a, uint32_t bytes) {
    asm volatile("mbarrier.arrive.expect_tx.shared.b64 _, [%0], %1;"
                 :: "r"(a), "r"(bytes) : "memory");
}
__device__ __forceinline__ void mb_arrive(uint32_t a) {
    asm volatile("mbarrier.arrive.shared.b64 _, [%0];" :: "r"(a) : "memory");
}
__device__ __forceinline__ void mb_wait(uint32_t a, uint32_t parity) {
    asm volatile(
        "{\n\t.reg .pred P;\n\t"
        "WL_%=:\n\t"
        "mbarrier.try_wait.parity.acquire.cta.shared::cta.b64 P, [%0], %1, 0x989680;\n\t"
        "@P bra.uni WD_%=;\n\t"
        "bra.uni WL_%=;\n\t"
        "WD_%=:\n\t}"
        :: "r"(a), "r"(parity) : "memory");
}
__device__ __forceinline__ void bulk_g2s(uint32_t dst, const void* src,
                                         uint32_t bytes, uint32_t mbar) {
    asm volatile(
        "cp.async.bulk.shared::cluster.global.mbarrier::complete_tx::bytes "
        "[%0], [%1], %2, [%3];"
        :: "r"(dst), "l"(src), "r"(bytes), "r"(mbar) : "memory");
}

// ---- mma / ldmatrix -------------------------------------------------------
__device__ __forceinline__ void mma16816(float d[4], const uint32_t a[4],
                                         const uint32_t b[2]) {
    asm volatile(
        "mma.sync.aligned.m16n8k16.row.col.f32.bf16.bf16.f32 "
        "{%0,%1,%2,%3}, {%4,%5,%6,%7}, {%8,%9}, {%0,%1,%2,%3};\n"
        : "+f"(d[0]), "+f"(d[1]), "+f"(d[2]), "+f"(d[3])
        : "r"(a[0]), "r"(a[1]), "r"(a[2]), "r"(a[3]), "r"(b[0]), "r"(b[1]));
}
__device__ __forceinline__ void ldsm_x4(uint32_t& r0, uint32_t& r1,
                                        uint32_t& r2, uint32_t& r3,
                                        uint32_t addr) {
    asm volatile("ldmatrix.sync.aligned.m8n8.x4.shared.b16 {%0,%1,%2,%3}, [%4];"
                 : "=r"(r0), "=r"(r1), "=r"(r2), "=r"(r3) : "r"(addr));
}

// ---------------------------------------------------------------------------
// Kernel 1: l2-normalize rows -> bf16 in SW128-swizzled tile layout.
// ---------------------------------------------------------------------------
__global__ void normalize_kernel(const float* __restrict__ left,
                                 const float* __restrict__ right) {
    int warp = threadIdx.x >> 5, lane = threadIdx.x & 31;
    int row = blockIdx.x * 8 + warp;          // 0..8191
    bool isL = row < B_SZ;
    int r = isL ? row : row - B_SZ;
    const float* src = (isL ? left : right) + (size_t)r * D_SZ;

    float4 v[8];
    float ss = 0.0f;
    #pragma unroll
    for (int i = 0; i < 8; ++i) {
        v[i] = ((const float4*)src)[lane + 32 * i];
        ss += v[i].x * v[i].x + v[i].y * v[i].y + v[i].z * v[i].z + v[i].w * v[i].w;
    }
    #pragma unroll
    for (int o = 16; o > 0; o >>= 1) ss += __shfl_xor_sync(0xffffffffu, ss, o);
    float inv = rsqrtf(fmaxf(ss, EPS_F));

    char* base;
    int rr;
    size_t tile_b;
    if (isL) {
        base = (char*)g_ln + (size_t)(r >> 7) * NKB * A_TILE_B;
        rr = r & 127;
        tile_b = A_TILE_B;
    } else {
        base = (char*)g_rn + (size_t)(r >> 8) * NKB * B_TILE_B;
        rr = r & 255;
        tile_b = B_TILE_B;
    }

    #pragma unroll
    for (int i = 0; i < 8; ++i) {
        __nv_bfloat162 h0 = __floats2bfloat162_rn(v[i].x * inv, v[i].y * inv);
        __nv_bfloat162 h1 = __floats2bfloat162_rn(v[i].z * inv, v[i].w * inv);
        uint2 pack;
        pack.x = *(const unsigned int*)&h0;
        pack.y = *(const unsigned int*)&h1;
        int f = lane + 32 * i;                // float4 index in row, 0..255
        int kb = f >> 4;                      // k-block 0..15
        int kc = (f & 15) * 8;                // byte offset in [0,128)
        uint32_t off = (uint32_t)(rr * 128 + (kc ^ ((rr & 7) << 4)));
        *(uint2*)(base + (size_t)kb * tile_b + off) = pack;
    }
    if (lane == 0 && isL) { g_rowsum[r] = 0.0f; g_colsum[r] = 0.0f; }
    if (blockIdx.x == 0 && threadIdx.x == 0) g_done = 0;
}

// ---------------------------------------------------------------------------
// Kernel 2: persistent bf16 GEMM. 456 full 128x256 tiles (3 per CTA) + 112
// half 128x128 tiles (CTAs 0..111). 16 compute warps (2x8, 64x32 warp tile)
// + 1 producer warp, 2-stage BK=128 pipeline. Inner loop software-pipelined:
// B fragments double-buffered across kk, A fragments rolling one mt ahead.
// Fused exp / rowsum / colsum / diag epilogue; last CTA computes the loss.
// ---------------------------------------------------------------------------
__global__ void __launch_bounds__(NTHREADS, 1)
gemm_stats_kernel(const float* __restrict__ temperature,
                  float* __restrict__ out) {
    extern __shared__ char dsm[];
    __shared__ float s_rl[NCW + 1], s_rr[NCW + 1];
    __shared__ int s_last;
    uint32_t sbase = smem_u32(dsm);
    const int tid = threadIdx.x, warp = tid >> 5, lane = tid & 31;
    const int c = blockIdx.x;

    uint32_t mb_full  = sbase + SM_CTRL;        // 2 x 8B
    uint32_t mb_empty = sbase + SM_CTRL + 32;   // 2 x 8B

    if (tid == 0) {
        #pragma unroll
        for (int s = 0; s < NSTAGE; ++s) {
            mb_init(mb_full + 8 * s, 1);
            mb_init(mb_empty + 8 * s, NCW);
        }
    }
    __syncthreads();

    if (warp == NCW) {
        // ---------------- producer warp ----------------
        if (lane == 0) {
            int g = 0;
            for (int j = 0; j < 3; ++j) {                  // full tiles
                int t = c + NSM * j;
                int bi = t >> 4, bj = t & 15;
                for (int kc = 0; kc < 8; ++kc, ++g) {
                    int s = g & 1;
                    if (g >= NSTAGE)
                        mb_wait(mb_empty + 8 * s, ((g >> 1) - 1) & 1);
                    uint32_t dst = sbase + s * STAGE_B;
                    mb_expect(mb_full + 8 * s, STAGE_B);
                    bulk_g2s(dst,
                             (const char*)g_ln + (size_t)(bi * 16 + kc * 2) * A_TILE_B,
                             A_CHUNK_B, mb_full + 8 * s);
                    bulk_g2s(dst + A_CHUNK_B,
                             (const char*)g_rn + (size_t)(bj * 16 + kc * 2) * B_TILE_B,
                             B_CHUNK_B, mb_full + 8 * s);
                }
            }
            if (c < NHALF) {                               // one half tile
                int t2 = NFULL + (c >> 1);
                int bi = t2 >> 4, bj = t2 & 15, h = c & 1;
                for (int kc = 0; kc < 8; ++kc, ++g) {
                    int s = g & 1;
                    mb_wait(mb_empty + 8 * s, ((g >> 1) - 1) & 1);
                    uint32_t dst = sbase + s * STAGE_B;
                    mb_expect(mb_full + 8 * s, A_CHUNK_B + 32768u);
                    bulk_g2s(dst,
                             (const char*)g_ln + (size_t)(bi * 16 + kc * 2) * A_TILE_B,
                             A_CHUNK_B, mb_full + 8 * s);
                    bulk_g2s(dst + A_CHUNK_B,
                             (const char*)g_rn + (size_t)(bj * 16 + kc * 2) * B_TILE_B
                                               + (size_t)h * 16384,
                             16384u, mb_full + 8 * s);
                    bulk_g2s(dst + A_CHUNK_B + 16384u,
                             (const char*)g_rn + (size_t)(bj * 16 + kc * 2 + 1) * B_TILE_B
                                               + (size_t)h * 16384,
                             16384u, mb_full + 8 * s);
                }
            }
        }
    } else {
        // ---------------- compute warps (2x8 grid, 64x32 full) ----------
        const int wr = warp >> 3;    // 0..1  (64-row slab)
        const int wc = warp & 7;     // 0..7
        const int grp = lane >> 2;   // 0..7
        const int qid = lane & 3;    // 0..3
        const float scale = __expf(temperature[0]);

        const int a_row_in = (lane & 7) + ((lane >> 3) & 1) * 8;
        const uint32_t a_koff = ((lane >> 4) & 1) * 16;
        const int b_n_in = (lane & 7) + ((lane >> 4) & 1) * 8;
        const uint32_t b_koff = ((lane >> 3) & 1) * 16;
        const uint32_t a_sw = (uint32_t)((a_row_in & 7) << 4);
        const uint32_t b_sw = (uint32_t)((b_n_in & 7) << 4);
        const uint32_t a_rowbase = (uint32_t)((wr * 64 + a_row_in) * 128);

        int g = 0;

        auto run_tile = [&](int bi, int col_base, auto ntc) {
            constexpr int NTN = decltype(ntc)::value;     // 4 (full) / 2 (half)
            constexpr int WCW = 8 * NTN;                  // warp col width
            constexpr int PRN = NTN / 2;                  // B ldsm count
            constexpr int WIDTH = 64 * NTN;               // tile col width
            constexpr uint32_t SUBB = (uint32_t)(WIDTH * 128); // B k64 sub-tile
            const uint32_t b_rowbase = (uint32_t)((wc * WCW + b_n_in) * 128);

            float acc[4][NTN][4];
            #pragma unroll
            for (int mt = 0; mt < 4; ++mt)
                #pragma unroll
                for (int nt = 0; nt < NTN; ++nt)
                    #pragma unroll
                    for (int k = 0; k < 4; ++k) acc[mt][nt][k] = 0.0f;

            for (int kc = 0; kc < 8; ++kc, ++g) {
                int s = g & 1;
                mb_wait(mb_full + 8 * s, (g >> 1) & 1);

                uint32_t sA = sbase + s * STAGE_B;
                uint32_t sB = sA + A_CHUNK_B;

                uint32_t bf[2][NTN][2];
                uint32_t af[2][4];

                auto loadB = [&](uint32_t dst[NTN][2], int kk) {
                    uint32_t subB = (uint32_t)(kk >> 2) * SUBB;
                    uint32_t b_col = ((b_koff | (uint32_t)((kk & 3) << 5)) ^ b_sw) + subB;
                    #pragma unroll
                    for (int pr = 0; pr < PRN; ++pr) {
                        uint32_t r0, r1, r2, r3;
                        ldsm_x4(r0, r1, r2, r3,
                                sB + b_rowbase + pr * 2048 + b_col);
                        dst[2 * pr][0] = r0;      dst[2 * pr][1] = r1;
                        dst[2 * pr + 1][0] = r2;  dst[2 * pr + 1][1] = r3;
                    }
                };
                auto loadA = [&](uint32_t dst[4], int kk, int mt) {
                    uint32_t subA = (uint32_t)(kk >> 2) * (uint32_t)A_TILE_B;
                    uint32_t a_col = ((a_koff | (uint32_t)((kk & 3) << 5)) ^ a_sw) + subA;
                    ldsm_x4(dst[0], dst[1], dst[2], dst[3],
                            sA + a_rowbase + mt * 2048 + a_col);
                };

                loadB(bf[0], 0);
                loadA(af[0], 0, 0);
                #pragma unroll
                for (int kk = 0; kk < 8; ++kk) {
                    const int cb = kk & 1;
                    if (kk < 7) loadB(bf[cb ^ 1], kk + 1);   // prefetch next B
                    #pragma unroll
                    for (int mt = 0; mt < 4; ++mt) {
                        const int ab = (kk * 4 + mt) & 1;
                        if (!(kk == 7 && mt == 3)) {         // prefetch next A
                            const int nmt = (mt + 1) & 3;
                            const int nkk = kk + (mt == 3 ? 1 : 0);
                            loadA(af[ab ^ 1], nkk, nmt);
                        }
                        #pragma unroll
                        for (int nt = 0; nt < NTN; ++nt)
                            mma16816(acc[mt][nt], af[ab], bf[cb][nt]);
                    }
                }
                if (lane == 0) mb_arrive(mb_empty + 8 * s);
            }

            // ---- per-tile epilogue ----
            #pragma unroll
            for (int mt = 0; mt < 4; ++mt)
                #pragma unroll
                for (int nt = 0; nt < NTN; ++nt)
                    #pragma unroll
                    for (int k = 0; k < 4; ++k)
                        acc[mt][nt][k] = fast_exp(fmaf(acc[mt][nt][k], scale, -scale));

            // row sums
            #pragma unroll
            for (int mt = 0; mt < 4; ++mt) {
                float s0 = 0.0f, s1 = 0.0f;
                #pragma unroll
                for (int nt = 0; nt < NTN; ++nt) {
                    s0 += acc[mt][nt][0] + acc[mt][nt][1];
                    s1 += acc[mt][nt][2] + acc[mt][nt][3];
                }
                s0 += __shfl_xor_sync(0xffffffffu, s0, 1);
                s0 += __shfl_xor_sync(0xffffffffu, s0, 2);
                s1 += __shfl_xor_sync(0xffffffffu, s1, 1);
                s1 += __shfl_xor_sync(0xffffffffu, s1, 2);
                if (qid == 0) {
                    int row = bi * BM + wr * 64 + mt * 16 + grp;
                    atomicAdd(&g_rowsum[row], s0);
                    atomicAdd(&g_rowsum[row + 8], s1);
                }
            }

            // col sums
            #pragma unroll
            for (int nt = 0; nt < NTN; ++nt) {
                float t0 = 0.0f, t1 = 0.0f;
                #pragma unroll
                for (int mt = 0; mt < 4; ++mt) {
                    t0 += acc[mt][nt][0] + acc[mt][nt][2];
                    t1 += acc[mt][nt][1] + acc[mt][nt][3];
                }
                t0 += __shfl_xor_sync(0xffffffffu, t0, 4);
                t0 += __shfl_xor_sync(0xffffffffu, t0, 8);
                t0 += __shfl_xor_sync(0xffffffffu, t0, 16);
                t1 += __shfl_xor_sync(0xffffffffu, t1, 4);
                t1 += __shfl_xor_sync(0xffffffffu, t1, 8);
                t1 += __shfl_xor_sync(0xffffffffu, t1, 16);
                if (grp == 0) {
                    int col = col_base + wc * WCW + nt * 8 + 2 * qid;
                    atomicAdd(&g_colsum[col], t0);
                    atomicAdd(&g_colsum[col + 1], t1);
                }
            }

            // diagonal: global row bi*128+lrow == global col col_base+lcol
            int doff = bi * BM - col_base;
            if (doff > -BM && doff < WIDTH) {
                #pragma unroll
                for (int mt = 0; mt < 4; ++mt) {
                    int lrow = wr * 64 + mt * 16 + grp;
                    #pragma unroll
                    for (int nt = 0; nt < NTN; ++nt) {
                        int lcol = wc * WCW + nt * 8 + 2 * qid;
                        if (lcol == lrow + doff)         g_diag[bi * BM + lrow]     = acc[mt][nt][0];
                        if (lcol + 1 == lrow + doff)     g_diag[bi * BM + lrow]     = acc[mt][nt][1];
                        if (lcol == lrow + 8 + doff)     g_diag[bi * BM + lrow + 8] = acc[mt][nt][2];
                        if (lcol + 1 == lrow + 8 + doff) g_diag[bi * BM + lrow + 8] = acc[mt][nt][3];
                    }
                }
            }
        };

        for (int j = 0; j < 3; ++j) {
            int t = c + NSM * j;
            run_tile(t >> 4, (t & 15) * 256, Int<4>{});
        }
        if (c < NHALF) {
            int t2 = NFULL + (c >> 1);
            run_tile(t2 >> 4, (t2 & 15) * 256 + (c & 1) * 128, Int<2>{});
        }
    }

    // ---- fused finalize: last CTA computes traces + loss ----
    __threadfence();
    __syncthreads();
    if (tid == 0) s_last = (atomicAdd(&g_done, 1) == NSM - 1) ? 1 : 0;
    __syncthreads();
    if (s_last) {
        float tl = 0.0f, tr = 0.0f;
        for (int i = tid; i < B_SZ; i += NTHREADS) {
            float d = __ldcg(&g_diag[i]);
            tl += __fdividef(d, __ldcg(&g_rowsum[i]));
            tr += __fdividef(d, __ldcg(&g_colsum[i]));
        }
        #pragma unroll
        for (int o = 16; o > 0; o >>= 1) {
            tl += __shfl_xor_sync(0xffffffffu, tl, o);
            tr += __shfl_xor_sync(0xffffffffu, tr, o);
        }
        if (lane == 0) { s_rl[warp] = tl; s_rr[warp] = tr; }
        __syncthreads();
        if (tid == 0) {
            float TL = 0.0f, TR = 0.0f;
            #pragma unroll
            for (int w = 0; w < NCW + 1; ++w) { TL += s_rl[w]; TR += s_rr[w]; }
            float logeps = logf(EPS_F);
            float log1m  = logf(1.0f - EPS_F);
            float ll = -(TL * log1m + ((float)B_SZ - TL) * logeps);
            float lr = -(TR * log1m + ((float)B_SZ - TR) * logeps);
            out[0] = (ll + lr) * 0.5f / (float)B_SZ;
        }
    }
}

// ---------------------------------------------------------------------------
extern "C" void kernel_launch(void* const* d_in, const int* in_sizes, int n_in,
                              void* d_out, int out_size) {
    const float* left  = (const float*)d_in[0];
    const float* right = (const float*)d_in[1];
    const float* temp  = (const float*)d_in[2];

    static bool attr_set = false;
    if (!attr_set) {
        cudaFuncSetAttribute(gemm_stats_kernel,
                             cudaFuncAttributeMaxDynamicSharedMemorySize,
                             DSMEM_TOTAL);
        attr_set = true;
    }

    normalize_kernel<<<1024, 256>>>(left, right);
    gemm_stats_kernel<<<NSM, NTHREADS, DSMEM_TOTAL>>>(temp, (float*)d_out);
}